// round 4
// baseline (speedup 1.0000x reference)
#include <cuda_runtime.h>
#include <cuda_fp16.h>
#include <stdint.h>

// ------------------------------------------------------------------
// Problem constants
// ------------------------------------------------------------------
#define M_TOTAL 8192      // B*S = 4*2048 tokens
#define N_TOTAL 4096      // OUT
#define K_TOTAL 4096      // IN
#define GRP     256

#define BM 128
#define BN 128
#define BK 64             // halves per K-chunk (128 bytes/row -> SW128)
#define KITERS (K_TOTAL / BK)   // 64

#define SMEM_BYTES 65536  // 2 buffers x (A 16KB + B 16KB)

// ------------------------------------------------------------------
// Scratch (device globals; no allocation allowed)
// ------------------------------------------------------------------
__device__ __half g_aq[(size_t)M_TOTAL * K_TOTAL];   // (q - zp), exact in fp16
__device__ __half g_w16[(size_t)N_TOTAL * K_TOTAL];  // (w - zero)*scale in fp16
__device__ float  g_sx[M_TOTAL];                     // per-token scale
__device__ int    g_w_is_int8;                       // 1 if weight buffer is int8 bytes

// ------------------------------------------------------------------
// helpers
// ------------------------------------------------------------------
__device__ __forceinline__ uint32_t smem_u32(const void* p) {
    uint32_t a;
    asm("{ .reg .u64 t; cvta.to.shared.u64 t, %1; cvt.u32.u64 %0, t; }"
        : "=r"(a) : "l"(p));
    return a;
}

__device__ __forceinline__ uint32_t swz(uint32_t off) {
    return off ^ ((off >> 3) & 0x70);
}

// ------------------------------------------------------------------
// Kernel 0: detect weight buffer dtype (int32-promoted vs raw int8).
// Samples 256 int32 words within the first 16 MB (valid under both
// interpretations). int32 weights all lie in [-8,7]; random int8 byte
// quadruplets essentially never do.
// ------------------------------------------------------------------
__global__ void sniff_kernel(const int* __restrict__ w) {
    __shared__ int bad;
    if (threadIdx.x == 0) bad = 0;
    __syncthreads();
    int v = w[threadIdx.x * 16000];
    if (v < -8 || v > 7) atomicOr(&bad, 1);
    __syncthreads();
    if (threadIdx.x == 0) g_w_is_int8 = bad;
}

// ------------------------------------------------------------------
// Kernel 1: per-token asymmetric int8 fake-quant -> (q - zp) in fp16
// ------------------------------------------------------------------
__global__ void __launch_bounds__(256) quant_kernel(const float* __restrict__ x) {
    const int t = blockIdx.x;
    const int tid = threadIdx.x;
    const float4* xp = (const float4*)x + (size_t)t * (K_TOTAL / 4);

    float4 v[4];
    float mn = 0.0f, mx = 0.0f;
#pragma unroll
    for (int i = 0; i < 4; i++) {
        v[i] = xp[i * 256 + tid];
        mn = fminf(mn, fminf(fminf(v[i].x, v[i].y), fminf(v[i].z, v[i].w)));
        mx = fmaxf(mx, fmaxf(fmaxf(v[i].x, v[i].y), fmaxf(v[i].z, v[i].w)));
    }
#pragma unroll
    for (int o = 16; o; o >>= 1) {
        mn = fminf(mn, __shfl_xor_sync(0xffffffffu, mn, o));
        mx = fmaxf(mx, __shfl_xor_sync(0xffffffffu, mx, o));
    }
    __shared__ float smn[8], smx[8], s_scale, s_zp;
    const int wid = tid >> 5, lid = tid & 31;
    if (lid == 0) { smn[wid] = mn; smx[wid] = mx; }
    __syncthreads();
    if (tid == 0) {
        float a = smn[0], b = smx[0];
#pragma unroll
        for (int i = 1; i < 8; i++) { a = fminf(a, smn[i]); b = fmaxf(b, smx[i]); }
        float scale = fmaxf((b - a) / 255.0f, 1.1920929e-07f);
        float zp = -128.0f - rintf(a / scale);
        zp = fminf(fmaxf(zp, -128.0f), 127.0f);
        s_scale = scale; s_zp = zp;
        g_sx[t] = scale;
    }
    __syncthreads();
    const float scale = s_scale, zp = s_zp;

    __half* aqp = g_aq + (size_t)t * K_TOTAL;
#pragma unroll
    for (int i = 0; i < 4; i++) {
        float qx = fminf(fmaxf(rintf(v[i].x / scale) + zp, -128.0f), 127.0f) - zp;
        float qy = fminf(fmaxf(rintf(v[i].y / scale) + zp, -128.0f), 127.0f) - zp;
        float qz = fminf(fmaxf(rintf(v[i].z / scale) + zp, -128.0f), 127.0f) - zp;
        float qw = fminf(fmaxf(rintf(v[i].w / scale) + zp, -128.0f), 127.0f) - zp;
        __half2 h0 = __floats2half2_rn(qx, qy);
        __half2 h1 = __floats2half2_rn(qz, qw);
        uint2 u;
        u.x = *reinterpret_cast<uint32_t*>(&h0);
        u.y = *reinterpret_cast<uint32_t*>(&h1);
        ((uint2*)aqp)[i * 256 + tid] = u;
    }
}

// ------------------------------------------------------------------
// Kernel 2: groupwise int4 weight dequant -> fp16 (dtype-adaptive)
// ------------------------------------------------------------------
__global__ void __launch_bounds__(256) wdq_kernel(const void* __restrict__ wraw,
                                                  const float* __restrict__ scales,
                                                  const float* __restrict__ zeros) {
    const int idx = blockIdx.x * 256 + threadIdx.x;
    const size_t base = (size_t)idx * 8;
    const int o = (int)(base >> 12);
    const int g = (int)((base & (K_TOTAL - 1)) >> 8);
    const float s = scales[o * (K_TOTAL / GRP) + g];
    const float z = zeros[o * (K_TOTAL / GRP) + g];

    float wv[8];
    if (g_w_is_int8) {
        const char4* wp = (const char4*)((const int8_t*)wraw + base);
        char4 c0 = wp[0], c1 = wp[1];
        wv[0] = c0.x; wv[1] = c0.y; wv[2] = c0.z; wv[3] = c0.w;
        wv[4] = c1.x; wv[5] = c1.y; wv[6] = c1.z; wv[7] = c1.w;
    } else {
        const int4* wp = (const int4*)((const int*)wraw + base);
        int4 a = wp[0], b = wp[1];
        wv[0] = (float)a.x; wv[1] = (float)a.y; wv[2] = (float)a.z; wv[3] = (float)a.w;
        wv[4] = (float)b.x; wv[5] = (float)b.y; wv[6] = (float)b.z; wv[7] = (float)b.w;
    }

    __half2 h0 = __floats2half2_rn((wv[0] - z) * s, (wv[1] - z) * s);
    __half2 h1 = __floats2half2_rn((wv[2] - z) * s, (wv[3] - z) * s);
    __half2 h2 = __floats2half2_rn((wv[4] - z) * s, (wv[5] - z) * s);
    __half2 h3 = __floats2half2_rn((wv[6] - z) * s, (wv[7] - z) * s);
    uint4 u;
    u.x = *reinterpret_cast<uint32_t*>(&h0);
    u.y = *reinterpret_cast<uint32_t*>(&h1);
    u.z = *reinterpret_cast<uint32_t*>(&h2);
    u.w = *reinterpret_cast<uint32_t*>(&h3);
    *((uint4*)(g_w16 + base)) = u;
}

// ------------------------------------------------------------------
// Kernel 3: HMMA (mma.sync m16n8k16) GEMM, 128x128 CTA tile,
// cp.async double-buffered SW128 SMEM, 8 warps, 64x32 warp tile.
// Fragments loaded with direct per-thread LDS.32 (conflict-free).
// ------------------------------------------------------------------
__global__ void __launch_bounds__(256) gemm_kernel(const float* __restrict__ bias,
                                                   float* __restrict__ out) {
    extern __shared__ char smem[];
    const uint32_t sb = smem_u32(smem);
    const int tid = threadIdx.x;
    const int lane = tid & 31, wid = tid >> 5;
    const int wm = wid >> 2, wn = wid & 3;           // warp grid 2 x 4
    const int g = lane >> 2, tg = lane & 3;
    const int row0 = blockIdx.y * BM;                // token (M)
    const int col0 = blockIdx.x * BN;                // out-feature (N)

    const uint4* Asrc = (const uint4*)g_aq  + (size_t)row0 * (K_TOTAL / 8);
    const uint4* Bsrc = (const uint4*)g_w16 + (size_t)col0 * (K_TOTAL / 8);

    float acc[4][4][4];
#pragma unroll
    for (int a = 0; a < 4; a++)
#pragma unroll
        for (int b = 0; b < 4; b++)
#pragma unroll
            for (int c = 0; c < 4; c++) acc[a][b][c] = 0.0f;

    auto load_tile = [&](int buf, int it) {
        const uint4* As = Asrc + it * (BK / 8);
        const uint4* Bs = Bsrc + it * (BK / 8);
        const uint32_t base = sb + buf * 32768;
#pragma unroll
        for (int i = 0; i < 4; i++) {
            int idx = i * 256 + tid;
            int r = idx >> 3, c = idx & 7;
            uint32_t sw = swz(r * 128 + c * 16);
            const void* ga = As + (size_t)r * 512 + c;
            const void* gb = Bs + (size_t)r * 512 + c;
            asm volatile("cp.async.cg.shared.global [%0], [%1], 16;"
                         :: "r"(base + sw), "l"(ga));
            asm volatile("cp.async.cg.shared.global [%0], [%1], 16;"
                         :: "r"(base + 16384 + sw), "l"(gb));
        }
        asm volatile("cp.async.commit_group;" ::: "memory");
    };

    load_tile(0, 0);

    for (int it = 0; it < KITERS; ++it) {
        asm volatile("cp.async.wait_group 0;" ::: "memory");
        __syncthreads();
        if (it + 1 < KITERS) load_tile((it + 1) & 1, it + 1);

        const char* base = smem + (it & 1) * 32768;
        const char* baseB = base + 16384;
#pragma unroll
        for (int kk = 0; kk < 4; kk++) {
            const uint32_t kb = kk * 32 + tg * 4;
            uint32_t aF[4][4], bF[4][2];
#pragma unroll
            for (int mi = 0; mi < 4; mi++) {
                const uint32_t rA = wm * 64 + mi * 16 + g;
                aF[mi][0] = *(const uint32_t*)(base + swz(rA * 128 + kb));
                aF[mi][1] = *(const uint32_t*)(base + swz((rA + 8) * 128 + kb));
                aF[mi][2] = *(const uint32_t*)(base + swz(rA * 128 + kb + 16));
                aF[mi][3] = *(const uint32_t*)(base + swz((rA + 8) * 128 + kb + 16));
            }
#pragma unroll
            for (int nj = 0; nj < 4; nj++) {
                const uint32_t rB = wn * 32 + nj * 8 + g;
                bF[nj][0] = *(const uint32_t*)(baseB + swz(rB * 128 + kb));
                bF[nj][1] = *(const uint32_t*)(baseB + swz(rB * 128 + kb + 16));
            }
#pragma unroll
            for (int mi = 0; mi < 4; mi++)
#pragma unroll
                for (int nj = 0; nj < 4; nj++)
                    asm volatile(
                        "mma.sync.aligned.m16n8k16.row.col.f32.f16.f16.f32 "
                        "{%0,%1,%2,%3},{%4,%5,%6,%7},{%8,%9},{%0,%1,%2,%3};"
                        : "+f"(acc[mi][nj][0]), "+f"(acc[mi][nj][1]),
                          "+f"(acc[mi][nj][2]), "+f"(acc[mi][nj][3])
                        : "r"(aF[mi][0]), "r"(aF[mi][1]), "r"(aF[mi][2]), "r"(aF[mi][3]),
                          "r"(bF[nj][0]), "r"(bF[nj][1]));
        }
        __syncthreads();
    }

    // epilogue: apply per-token scale + bias, direct GMEM stores (float2)
    const int mrow = row0 + wm * 64 + g;
    const int ncol = col0 + wn * 32 + tg * 2;
#pragma unroll
    for (int mi = 0; mi < 4; mi++) {
        const int r = mrow + mi * 16;
        const float s0 = g_sx[r], s1 = g_sx[r + 8];
#pragma unroll
        for (int nj = 0; nj < 4; nj++) {
            const int c = ncol + nj * 8;
            const float b0 = bias[c], b1 = bias[c + 1];
            float2 v0 = make_float2(acc[mi][nj][0] * s0 + b0,
                                    acc[mi][nj][1] * s0 + b1);
            float2 v1 = make_float2(acc[mi][nj][2] * s1 + b0,
                                    acc[mi][nj][3] * s1 + b1);
            *(float2*)(out + (size_t)r * N_TOTAL + c) = v0;
            *(float2*)(out + (size_t)(r + 8) * N_TOTAL + c) = v1;
        }
    }
}

// ------------------------------------------------------------------
// launch
// ------------------------------------------------------------------
extern "C" void kernel_launch(void* const* d_in, const int* in_sizes, int n_in,
                              void* d_out, int out_size) {
    const float* x      = (const float*)d_in[0];
    const void*  w      = d_in[1];
    const float* scales = (const float*)d_in[2];
    const float* zeros  = (const float*)d_in[3];
    const float* bias   = (const float*)d_in[4];
    float* out = (float*)d_out;

    sniff_kernel<<<1, 256>>>((const int*)w);
    quant_kernel<<<M_TOTAL, 256>>>(x);
    wdq_kernel<<<(N_TOTAL * (K_TOTAL / 8)) / 256, 256>>>(w, scales, zeros);

    cudaFuncSetAttribute(gemm_kernel, cudaFuncAttributeMaxDynamicSharedMemorySize,
                         SMEM_BYTES);
    gemm_kernel<<<dim3(N_TOTAL / BN, M_TOTAL / BM), 256, SMEM_BYTES>>>(bias, out);
}

// round 5
// speedup vs baseline: 1.0798x; 1.0798x over previous
#include <cuda_runtime.h>
#include <cuda_fp16.h>
#include <stdint.h>

// ------------------------------------------------------------------
// Problem constants
// ------------------------------------------------------------------
#define M_TOTAL 8192      // B*S = 4*2048 tokens
#define N_TOTAL 4096      // OUT
#define K_TOTAL 4096      // IN
#define GRP     256

#define BM 128
#define BN 128
#define BK 64             // halves per K-chunk (128 bytes/row -> SW128)
#define KITERS (K_TOTAL / BK)   // 64
#define STAGES 3
#define STAGE_BYTES 32768       // A 16KB + B 16KB

#define SMEM_BYTES (STAGES * STAGE_BYTES)   // 96 KB

// ------------------------------------------------------------------
// Scratch (device globals; no allocation allowed)
// ------------------------------------------------------------------
__device__ __half g_aq[(size_t)M_TOTAL * K_TOTAL];   // (q - zp), exact in fp16
__device__ __half g_w16[(size_t)N_TOTAL * K_TOTAL];  // (w - zero)*scale in fp16
__device__ float  g_sx[M_TOTAL];                     // per-token scale
__device__ int    g_w_is_int8;                       // 1 if weight buffer is int8 bytes

// ------------------------------------------------------------------
// helpers
// ------------------------------------------------------------------
__device__ __forceinline__ uint32_t smem_u32(const void* p) {
    uint32_t a;
    asm("{ .reg .u64 t; cvta.to.shared.u64 t, %1; cvt.u32.u64 %0, t; }"
        : "=r"(a) : "l"(p));
    return a;
}

__device__ __forceinline__ uint32_t swz(uint32_t off) {
    return off ^ ((off >> 3) & 0x70);
}

__device__ __forceinline__ void ldsm_x4(uint32_t addr, uint32_t& r0, uint32_t& r1,
                                        uint32_t& r2, uint32_t& r3) {
    asm volatile("ldmatrix.sync.aligned.m8n8.x4.shared.b16 {%0,%1,%2,%3}, [%4];"
                 : "=r"(r0), "=r"(r1), "=r"(r2), "=r"(r3) : "r"(addr));
}

// ------------------------------------------------------------------
// Kernel 0: detect weight buffer dtype (int32-promoted vs raw int8)
// ------------------------------------------------------------------
__global__ void sniff_kernel(const int* __restrict__ w) {
    __shared__ int bad;
    if (threadIdx.x == 0) bad = 0;
    __syncthreads();
    int v = w[threadIdx.x * 16000];
    if (v < -8 || v > 7) atomicOr(&bad, 1);
    __syncthreads();
    if (threadIdx.x == 0) g_w_is_int8 = bad;
}

// ------------------------------------------------------------------
// Kernel 1: per-token asymmetric int8 fake-quant -> (q - zp) in fp16
// ------------------------------------------------------------------
__global__ void __launch_bounds__(256) quant_kernel(const float* __restrict__ x) {
    const int t = blockIdx.x;
    const int tid = threadIdx.x;
    const float4* xp = (const float4*)x + (size_t)t * (K_TOTAL / 4);

    float4 v[4];
    float mn = 0.0f, mx = 0.0f;
#pragma unroll
    for (int i = 0; i < 4; i++) {
        v[i] = xp[i * 256 + tid];
        mn = fminf(mn, fminf(fminf(v[i].x, v[i].y), fminf(v[i].z, v[i].w)));
        mx = fmaxf(mx, fmaxf(fmaxf(v[i].x, v[i].y), fmaxf(v[i].z, v[i].w)));
    }
#pragma unroll
    for (int o = 16; o; o >>= 1) {
        mn = fminf(mn, __shfl_xor_sync(0xffffffffu, mn, o));
        mx = fmaxf(mx, __shfl_xor_sync(0xffffffffu, mx, o));
    }
    __shared__ float smn[8], smx[8], s_scale, s_zp;
    const int wid = tid >> 5, lid = tid & 31;
    if (lid == 0) { smn[wid] = mn; smx[wid] = mx; }
    __syncthreads();
    if (tid == 0) {
        float a = smn[0], b = smx[0];
#pragma unroll
        for (int i = 1; i < 8; i++) { a = fminf(a, smn[i]); b = fmaxf(b, smx[i]); }
        float scale = fmaxf((b - a) / 255.0f, 1.1920929e-07f);
        float zp = -128.0f - rintf(a / scale);
        zp = fminf(fmaxf(zp, -128.0f), 127.0f);
        s_scale = scale; s_zp = zp;
        g_sx[t] = scale;
    }
    __syncthreads();
    const float scale = s_scale, zp = s_zp;

    __half* aqp = g_aq + (size_t)t * K_TOTAL;
#pragma unroll
    for (int i = 0; i < 4; i++) {
        float qx = fminf(fmaxf(rintf(v[i].x / scale) + zp, -128.0f), 127.0f) - zp;
        float qy = fminf(fmaxf(rintf(v[i].y / scale) + zp, -128.0f), 127.0f) - zp;
        float qz = fminf(fmaxf(rintf(v[i].z / scale) + zp, -128.0f), 127.0f) - zp;
        float qw = fminf(fmaxf(rintf(v[i].w / scale) + zp, -128.0f), 127.0f) - zp;
        __half2 h0 = __floats2half2_rn(qx, qy);
        __half2 h1 = __floats2half2_rn(qz, qw);
        uint2 u;
        u.x = *reinterpret_cast<uint32_t*>(&h0);
        u.y = *reinterpret_cast<uint32_t*>(&h1);
        ((uint2*)aqp)[i * 256 + tid] = u;
    }
}

// ------------------------------------------------------------------
// Kernel 2: groupwise int4 weight dequant -> fp16 (dtype-adaptive)
// ------------------------------------------------------------------
__global__ void __launch_bounds__(256) wdq_kernel(const void* __restrict__ wraw,
                                                  const float* __restrict__ scales,
                                                  const float* __restrict__ zeros) {
    const int idx = blockIdx.x * 256 + threadIdx.x;
    const size_t base = (size_t)idx * 8;
    const int o = (int)(base >> 12);
    const int g = (int)((base & (K_TOTAL - 1)) >> 8);
    const float s = scales[o * (K_TOTAL / GRP) + g];
    const float z = zeros[o * (K_TOTAL / GRP) + g];

    float wv[8];
    if (g_w_is_int8) {
        const char4* wp = (const char4*)((const int8_t*)wraw + base);
        char4 c0 = wp[0], c1 = wp[1];
        wv[0] = c0.x; wv[1] = c0.y; wv[2] = c0.z; wv[3] = c0.w;
        wv[4] = c1.x; wv[5] = c1.y; wv[6] = c1.z; wv[7] = c1.w;
    } else {
        const int4* wp = (const int4*)((const int*)wraw + base);
        int4 a = wp[0], b = wp[1];
        wv[0] = (float)a.x; wv[1] = (float)a.y; wv[2] = (float)a.z; wv[3] = (float)a.w;
        wv[4] = (float)b.x; wv[5] = (float)b.y; wv[6] = (float)b.z; wv[7] = (float)b.w;
    }

    __half2 h0 = __floats2half2_rn((wv[0] - z) * s, (wv[1] - z) * s);
    __half2 h1 = __floats2half2_rn((wv[2] - z) * s, (wv[3] - z) * s);
    __half2 h2 = __floats2half2_rn((wv[4] - z) * s, (wv[5] - z) * s);
    __half2 h3 = __floats2half2_rn((wv[6] - z) * s, (wv[7] - z) * s);
    uint4 u;
    u.x = *reinterpret_cast<uint32_t*>(&h0);
    u.y = *reinterpret_cast<uint32_t*>(&h1);
    u.z = *reinterpret_cast<uint32_t*>(&h2);
    u.w = *reinterpret_cast<uint32_t*>(&h3);
    *((uint4*)(g_w16 + base)) = u;
}

// ------------------------------------------------------------------
// Kernel 3: HMMA GEMM, 128x128 CTA tile, 3-stage cp.async pipeline,
// ldmatrix.x4 fragment loads, 8 warps (2x4), 64x32 warp tile.
// ------------------------------------------------------------------
__global__ void __launch_bounds__(256) gemm_kernel(const float* __restrict__ bias,
                                                   float* __restrict__ out) {
    extern __shared__ char smem[];
    const uint32_t sb = smem_u32(smem);
    const int tid = threadIdx.x;
    const int lane = tid & 31, wid = tid >> 5;
    const int wm = wid >> 2, wn = wid & 3;           // warp grid 2 x 4
    const int g = lane >> 2, tg = lane & 3;
    const int row0 = blockIdx.y * BM;                // token (M)
    const int col0 = blockIdx.x * BN;                // out-feature (N)

    const uint4* Asrc = (const uint4*)g_aq  + (size_t)row0 * (K_TOTAL / 8);
    const uint4* Bsrc = (const uint4*)g_w16 + (size_t)col0 * (K_TOTAL / 8);

    float acc[4][4][4];
#pragma unroll
    for (int a = 0; a < 4; a++)
#pragma unroll
        for (int b = 0; b < 4; b++)
#pragma unroll
            for (int c = 0; c < 4; c++) acc[a][b][c] = 0.0f;

    // per-thread cp.async source/dest (4 x 16B per operand per tile)
    const int ldr = tid >> 3, ldc = tid & 7;         // 32 rows x 8 cols of 16B
    const uint32_t ldsw = swz(ldr * 128 + ldc * 16);

    auto load_tile = [&](int buf, int it) {
        const uint4* As = Asrc + it * (BK / 8) + (size_t)ldr * 512 + ldc;
        const uint4* Bs = Bsrc + it * (BK / 8) + (size_t)ldr * 512 + ldc;
        const uint32_t base = sb + buf * STAGE_BYTES + ldsw;
#pragma unroll
        for (int i = 0; i < 4; i++) {
            asm volatile("cp.async.cg.shared.global [%0], [%1], 16;"
                         :: "r"(base + i * 4096), "l"(As + (size_t)i * 32 * 512));
            asm volatile("cp.async.cg.shared.global [%0], [%1], 16;"
                         :: "r"(base + 16384 + i * 4096), "l"(Bs + (size_t)i * 32 * 512));
        }
        asm volatile("cp.async.commit_group;" ::: "memory");
    };

    // ldmatrix lane address components
    const uint32_t aRow = wm * 64 + (lane & 15);     // lanes 0-15: m rows, 16-31: +k8
    const uint32_t bRow = wn * 32 + (lane & 15);
    const uint32_t kHalfB = (lane >> 4) << 3;        // 0 or 8 halves

    load_tile(0, 0);
    load_tile(1, 1);

    for (int it = 0; it < KITERS; ++it) {
        asm volatile("cp.async.wait_group 1;" ::: "memory");
        __syncthreads();
        if (it + 2 < KITERS) load_tile((it + 2) % STAGES, it + 2);

        const uint32_t base = sb + (it % STAGES) * STAGE_BYTES;
        const uint32_t baseB = base + 16384;
#pragma unroll
        for (int kk = 0; kk < 4; kk++) {
            const uint32_t kc = kk * 16 + kHalfB;    // half index within BK
            uint32_t aF[4][4], bF[4][2];
#pragma unroll
            for (int mi = 0; mi < 4; mi++) {
                uint32_t off = swz((aRow + mi * 16) * 128 + kc * 2);
                ldsm_x4(base + off, aF[mi][0], aF[mi][1], aF[mi][2], aF[mi][3]);
            }
#pragma unroll
            for (int j = 0; j < 2; j++) {
                uint32_t off = swz((bRow + j * 16) * 128 + kc * 2);
                uint32_t r0, r1, r2, r3;
                ldsm_x4(baseB + off, r0, r1, r2, r3);
                bF[2 * j][0] = r0; bF[2 * j][1] = r2;
                bF[2 * j + 1][0] = r1; bF[2 * j + 1][1] = r3;
            }
#pragma unroll
            for (int mi = 0; mi < 4; mi++)
#pragma unroll
                for (int nj = 0; nj < 4; nj++)
                    asm volatile(
                        "mma.sync.aligned.m16n8k16.row.col.f32.f16.f16.f32 "
                        "{%0,%1,%2,%3},{%4,%5,%6,%7},{%8,%9},{%0,%1,%2,%3};"
                        : "+f"(acc[mi][nj][0]), "+f"(acc[mi][nj][1]),
                          "+f"(acc[mi][nj][2]), "+f"(acc[mi][nj][3])
                        : "r"(aF[mi][0]), "r"(aF[mi][1]), "r"(aF[mi][2]), "r"(aF[mi][3]),
                          "r"(bF[nj][0]), "r"(bF[nj][1]));
        }
    }

    // epilogue: apply per-token scale + bias, direct GMEM stores (float2)
    const int mrow = row0 + wm * 64 + g;
    const int ncol = col0 + wn * 32 + tg * 2;
#pragma unroll
    for (int mi = 0; mi < 4; mi++) {
        const int r = mrow + mi * 16;
        const float s0 = g_sx[r], s1 = g_sx[r + 8];
#pragma unroll
        for (int nj = 0; nj < 4; nj++) {
            const int c = ncol + nj * 8;
            const float b0 = bias[c], b1 = bias[c + 1];
            float2 v0 = make_float2(acc[mi][nj][0] * s0 + b0,
                                    acc[mi][nj][1] * s0 + b1);
            float2 v1 = make_float2(acc[mi][nj][2] * s1 + b0,
                                    acc[mi][nj][3] * s1 + b1);
            *(float2*)(out + (size_t)r * N_TOTAL + c) = v0;
            *(float2*)(out + (size_t)(r + 8) * N_TOTAL + c) = v1;
        }
    }
}

// ------------------------------------------------------------------
// launch
// ------------------------------------------------------------------
extern "C" void kernel_launch(void* const* d_in, const int* in_sizes, int n_in,
                              void* d_out, int out_size) {
    const float* x      = (const float*)d_in[0];
    const void*  w      = d_in[1];
    const float* scales = (const float*)d_in[2];
    const float* zeros  = (const float*)d_in[3];
    const float* bias   = (const float*)d_in[4];
    float* out = (float*)d_out;

    sniff_kernel<<<1, 256>>>((const int*)w);
    quant_kernel<<<M_TOTAL, 256>>>(x);
    wdq_kernel<<<(N_TOTAL * (K_TOTAL / 8)) / 256, 256>>>(w, scales, zeros);

    cudaFuncSetAttribute(gemm_kernel, cudaFuncAttributeMaxDynamicSharedMemorySize,
                         SMEM_BYTES);
    gemm_kernel<<<dim3(N_TOTAL / BN, M_TOTAL / BM), 256, SMEM_BYTES>>>(bias, out);
}